// round 15
// baseline (speedup 1.0000x reference)
#include <cuda_runtime.h>
#include <cuda_fp16.h>
#include <math.h>
#include <stdint.h>

#define SQB 16384
#define SKK 4096
#define DDK 512
#define DVV 256

// ---------------- scratch ----------------
__device__ __align__(256) __half g_Yh[SKK * DDK];
__device__ __align__(256) __half g_Zh[SKK * DDK];
__device__ __align__(256) __half g_Wkh[DDK * DDK];
__device__ __align__(256) __half g_Wvh[DVV * DDK];
__device__ __align__(256) __half g_Sh[(long long)SQB * SKK];   // scores fp16
__device__ __align__(256) __half g_Xh[(long long)SQB * DDK];
__device__ __align__(256) __half g_Kh[SKK * DDK];              // projected K fp16
__device__ __align__(256) __half g_Vh[SKK * DVV];              // projected V fp16
__device__ __align__(256) __half g_Vth[DVV * SKK];             // V^T fp16
__device__ __align__(256) __half g_Ph[(long long)SQB * SKK];   // probs fp16

// ---------------- helpers ----------------
__device__ __forceinline__ uint32_t smem_u32(const void* p) {
    uint32_t a;
    asm("{ .reg .u64 t; cvta.to.shared.u64 t, %1; cvt.u32.u64 %0, t; }" : "=r"(a) : "l"(p));
    return a;
}
__device__ __forceinline__ void cp16(uint32_t s, const void* g) {
    asm volatile("cp.async.cg.shared.global [%0], [%1], 16;"
                 :: "r"(s), "l"(__cvta_generic_to_global(g)) : "memory");
}
#define CP_COMMIT() asm volatile("cp.async.commit_group;" ::: "memory")
#define CP_WAIT(n)  asm volatile("cp.async.wait_group %0;" :: "n"(n) : "memory")

#define LDSM4(r, a) \
    asm volatile("ldmatrix.sync.aligned.m8n8.x4.shared.b16 {%0,%1,%2,%3}, [%4];" \
                 : "=r"((r)[0]), "=r"((r)[1]), "=r"((r)[2]), "=r"((r)[3]) : "r"(a))

#define MMA_F16(d, a, b) \
    asm volatile("mma.sync.aligned.m16n8k16.row.col.f32.f16.f16.f32 " \
                 "{%0,%1,%2,%3}, {%4,%5,%6,%7}, {%8,%9}, {%0,%1,%2,%3};" \
                 : "+f"((d)[0]), "+f"((d)[1]), "+f"((d)[2]), "+f"((d)[3]) \
                 : "r"((a)[0]), "r"((a)[1]), "r"((a)[2]), "r"((a)[3]), \
                   "r"((b)[0]), "r"((b)[1]))

// ---------------- HMMA NT GEMM, single fp16, 128x128 CTA, KC=64, 3 stages --
// C[M,N] = A[M,K] * B[N,K]^T * scale ; output fp32 or fp16 (template)
// 8 warps as 2(M) x 4(N), each warp 64x32. 2 CTA/SM.
#define KC 64
#define ROWB 144                // 128B data + 16B pad per smem row
#define PLANE (128 * ROWB)      // 18432 B
#define OFF_A  0
#define OFF_B  (1 * PLANE)
#define STAGE  (2 * PLANE)      // 36864 B
#define NSTG   3
#define SMEMSZ (NSTG * STAGE)   // 110592 B

__device__ __forceinline__ void load_stage(
    uint32_t base, int tid, int kc0, int Kdim,
    const __half* __restrict__ A, const __half* __restrict__ B,
    long long m0, long long n0)
{
#pragma unroll
    for (int it = 0; it < 4; it++) {
        const int j = tid + it * 256;
        const int row = j >> 3;
        const int part = j & 7;
        const uint32_t off = (uint32_t)row * ROWB + part * 16;
        cp16(base + OFF_A + off, A + (m0 + row) * (long long)Kdim + kc0 + part * 8);
        cp16(base + OFF_B + off, B + (n0 + row) * (long long)Kdim + kc0 + part * 8);
    }
    CP_COMMIT();
}

template <int HALF_OUT>
__global__ __launch_bounds__(256)
void hmma_gemm_nt(const __half* __restrict__ A, const __half* __restrict__ B,
                  void* __restrict__ Cv, int Kdim, int ldc, float scale)
{
    extern __shared__ char sm[];
    const uint32_t sb = smem_u32(sm);

    const int tid  = threadIdx.x;
    const int lane = tid & 31;
    const int wid  = tid >> 5;
    const int wm   = wid & 1;    // 2 warps along M
    const int wn   = wid >> 1;   // 4 warps along N
    const long long m0 = (long long)blockIdx.y * 128;
    const long long n0 = (long long)blockIdx.x * 128;

    float acc[4][4][4];
#pragma unroll
    for (int i = 0; i < 4; i++)
#pragma unroll
        for (int j = 0; j < 4; j++)
#pragma unroll
            for (int k = 0; k < 4; k++) acc[i][j][k] = 0.f;

    const int NC = Kdim / KC;

    // prologue: fill 3 stages (chunks 0..2; guard small K)
    load_stage(sb, tid, 0, Kdim, A, B, m0, n0);
    if (1 < NC) load_stage(sb + STAGE,     tid, KC,     Kdim, A, B, m0, n0);
    if (2 < NC) load_stage(sb + 2 * STAGE, tid, 2 * KC, Kdim, A, B, m0, n0);

    const int g = lane >> 3;
    const int r = lane & 7;

    int stc = 0;  // stage of chunk c
    for (int c = 0; c < NC; c++) {
        const uint32_t base = sb + stc * STAGE;
        // ensure chunk c's group is complete; keep up to 2 newer in flight
        if (c + 2 < NC)      { CP_WAIT(2); }
        else if (c + 1 < NC) { CP_WAIT(1); }
        else                 { CP_WAIT(0); }
        __syncthreads();

#pragma unroll
        for (int ks = 0; ks < 4; ks++) {
            uint32_t a_f[4][4], b_f[4][2];
#pragma unroll
            for (int mi = 0; mi < 4; mi++) {
                const uint32_t row = wm * 64 + mi * 16 + (g & 1) * 8 + r;
                const uint32_t cb  = ks * 32 + (g >> 1) * 16;
                LDSM4(a_f[mi], base + OFF_A + row * ROWB + cb);
            }
#pragma unroll
            for (int np = 0; np < 2; np++) {
                const uint32_t row = wn * 32 + np * 16 + (g >> 1) * 8 + r;
                const uint32_t cb  = ks * 32 + (g & 1) * 16;
                uint32_t t[4];
                LDSM4(t, base + OFF_B + row * ROWB + cb);
                b_f[np * 2][0] = t[0]; b_f[np * 2][1] = t[1];
                b_f[np * 2 + 1][0] = t[2]; b_f[np * 2 + 1][1] = t[3];
            }
#pragma unroll
            for (int mi = 0; mi < 4; mi++)
#pragma unroll
                for (int ni = 0; ni < 4; ni++)
                    MMA_F16(acc[mi][ni], a_f[mi], b_f[ni]);
        }
        __syncthreads();
        if (c + NSTG < NC)
            load_stage(base, tid, (c + NSTG) * KC, Kdim, A, B, m0, n0);
        stc = (stc == NSTG - 1) ? 0 : stc + 1;
    }

    // epilogue
#pragma unroll
    for (int mi = 0; mi < 4; mi++)
#pragma unroll
        for (int ni = 0; ni < 4; ni++) {
            const long long row = m0 + wm * 64 + mi * 16 + (lane >> 2);
            const long long col = n0 + wn * 32 + ni * 8 + 2 * (lane & 3);
            if (HALF_OUT) {
                __half* C = (__half*)Cv;
                __half2 h0 = __floats2half2_rn(acc[mi][ni][0] * scale,
                                               acc[mi][ni][1] * scale);
                __half2 h1 = __floats2half2_rn(acc[mi][ni][2] * scale,
                                               acc[mi][ni][3] * scale);
                *(__half2*)&C[row * ldc + col]       = h0;
                *(__half2*)&C[(row + 8) * ldc + col] = h1;
            } else {
                float* C = (float*)Cv;
                float2 v0 = make_float2(acc[mi][ni][0] * scale, acc[mi][ni][1] * scale);
                float2 v1 = make_float2(acc[mi][ni][2] * scale, acc[mi][ni][3] * scale);
                *(float2*)&C[row * ldc + col]       = v0;
                *(float2*)&C[(row + 8) * ldc + col] = v1;
            }
        }
}

// ---------------- conversion kernels ----------------
__device__ __forceinline__ uint32_t packh2(__half a, __half b) {
    return (uint32_t)__half_as_ushort(a) | ((uint32_t)__half_as_ushort(b) << 16);
}

__global__ __launch_bounds__(256)
void tohalf_kernel(const float* __restrict__ in, __half* __restrict__ out)
{
    const long long i = (long long)blockIdx.x * 256 + threadIdx.x;
    float4 v = ((const float4*)in)[i];
    ((uint2*)out)[i] = make_uint2(packh2(__float2half_rn(v.x), __float2half_rn(v.y)),
                                  packh2(__float2half_rn(v.z), __float2half_rn(v.w)));
}

// V [4096,256] fp16 -> V^T [256,4096] fp16, 32x32 smem tile transpose
__global__ __launch_bounds__(256)
void vtrans_kernel(const __half* __restrict__ V, __half* __restrict__ th)
{
    __shared__ __half t[32][34];
    const int x = threadIdx.x & 31;
    const int y = threadIdx.x >> 5;
    const int k0 = blockIdx.x * 32;
    const int n0 = blockIdx.y * 32;
#pragma unroll
    for (int i = 0; i < 4; i++)
        t[y + i * 8][x] = V[(long long)(k0 + y + i * 8) * 256 + n0 + x];
    __syncthreads();
#pragma unroll
    for (int i = 0; i < 4; i++)
        th[(long long)(n0 + y + i * 8) * 4096 + k0 + x] = t[x][y + i * 8];
}

// ---------------- softmax (fp16 in) -> P fp16 ----------------
__global__ __launch_bounds__(256)
void softmax_half_kernel(const __half* __restrict__ S, __half* __restrict__ Ph)
{
    const long long rbase = (long long)blockIdx.x * 4096;
    const __half* p = S + rbase;
    const int tid = threadIdx.x, wid = tid >> 5, lane = tid & 31;

    float v[16];
#pragma unroll
    for (int i = 0; i < 4; i++) {
        uint2 u = *(const uint2*)&p[i * 1024 + tid * 4];
        __half2 h0 = *(__half2*)&u.x;
        __half2 h1 = *(__half2*)&u.y;
        float2 f0 = __half22float2(h0);
        float2 f1 = __half22float2(h1);
        v[i * 4 + 0] = f0.x; v[i * 4 + 1] = f0.y;
        v[i * 4 + 2] = f1.x; v[i * 4 + 3] = f1.y;
    }

    float m = -INFINITY;
#pragma unroll
    for (int i = 0; i < 16; i++) m = fmaxf(m, v[i]);
#pragma unroll
    for (int o = 16; o > 0; o >>= 1) m = fmaxf(m, __shfl_xor_sync(0xffffffffu, m, o));

    __shared__ float redm[8], reds[8];
    if (lane == 0) redm[wid] = m;
    __syncthreads();
    m = redm[0];
#pragma unroll
    for (int i = 1; i < 8; i++) m = fmaxf(m, redm[i]);

    float s = 0.f;
#pragma unroll
    for (int i = 0; i < 16; i++) { v[i] = __expf(v[i] - m); s += v[i]; }
#pragma unroll
    for (int o = 16; o > 0; o >>= 1) s += __shfl_xor_sync(0xffffffffu, s, o);
    if (lane == 0) reds[wid] = s;
    __syncthreads();
    s = 0.f;
#pragma unroll
    for (int i = 0; i < 8; i++) s += reds[i];
    const float inv = 1.0f / s;

#pragma unroll
    for (int i = 0; i < 4; i++) {
        __half h0 = __float2half_rn(v[i * 4 + 0] * inv);
        __half h1 = __float2half_rn(v[i * 4 + 1] * inv);
        __half h2 = __float2half_rn(v[i * 4 + 2] * inv);
        __half h3 = __float2half_rn(v[i * 4 + 3] * inv);
        const long long off = rbase + i * 1024 + tid * 4;
        *(uint2*)&Ph[off] = make_uint2(packh2(h0, h1), packh2(h2, h3));
    }
}

// ---------------------------------------------------------------------------
extern "C" void kernel_launch(void* const* d_in, const int* in_sizes, int n_in,
                              void* d_out, int out_size)
{
    (void)in_sizes; (void)n_in; (void)out_size;
    const float* X  = (const float*)d_in[0];
    const float* Y  = (const float*)d_in[1];
    const float* Z  = (const float*)d_in[2];
    const float* Wk = (const float*)d_in[3];
    const float* Wv = (const float*)d_in[4];
    float* out = (float*)d_out;

    __half *Yh, *Zh, *Wkh, *Wvh, *Sh, *Xh, *Kh, *Vh, *Vth, *Ph;
    cudaGetSymbolAddress((void**)&Yh,  g_Yh);
    cudaGetSymbolAddress((void**)&Zh,  g_Zh);
    cudaGetSymbolAddress((void**)&Wkh, g_Wkh);
    cudaGetSymbolAddress((void**)&Wvh, g_Wvh);
    cudaGetSymbolAddress((void**)&Sh,  g_Sh);
    cudaGetSymbolAddress((void**)&Xh,  g_Xh);
    cudaGetSymbolAddress((void**)&Kh,  g_Kh);
    cudaGetSymbolAddress((void**)&Vh,  g_Vh);
    cudaGetSymbolAddress((void**)&Vth, g_Vth);
    cudaGetSymbolAddress((void**)&Ph,  g_Ph);

    cudaFuncSetAttribute(hmma_gemm_nt<0>, cudaFuncAttributeMaxDynamicSharedMemorySize, SMEMSZ);
    cudaFuncSetAttribute(hmma_gemm_nt<1>, cudaFuncAttributeMaxDynamicSharedMemorySize, SMEMSZ);

    const float rs = 0.0441941738241592f;  // 1/sqrt(512)

    // fp32 -> fp16 conversions of raw inputs
    tohalf_kernel<<<(SQB * DDK) / 1024, 256>>>(X, Xh);
    tohalf_kernel<<<(SKK * DDK) / 1024, 256>>>(Y, Yh);
    tohalf_kernel<<<(SKK * DDK) / 1024, 256>>>(Z, Zh);
    tohalf_kernel<<<(DDK * DDK) / 1024, 256>>>(Wk, Wkh);
    tohalf_kernel<<<(DVV * DDK) / 1024, 256>>>(Wv, Wvh);

    // Projections on HMMA (fp16 in, fp32 accum, fp16 out)
    hmma_gemm_nt<1><<<dim3(DDK / 128, SKK / 128), 256, SMEMSZ>>>(
        Yh, Wkh, Kh, DDK, DDK, 1.f);
    hmma_gemm_nt<1><<<dim3(DVV / 128, SKK / 128), 256, SMEMSZ>>>(
        Zh, Wvh, Vh, DDK, DVV, 1.f);

    // V^T (fp16)
    vtrans_kernel<<<dim3(SKK / 32, DVV / 32), 256>>>(Vh, Vth);

    // S = X K^T * rs
    hmma_gemm_nt<1><<<dim3(SKK / 128, SQB / 128), 256, SMEMSZ>>>(
        Xh, Kh, Sh, DDK, SKK, rs);

    // softmax (fp16 in) -> P fp16
    softmax_half_kernel<<<SQB, 256>>>(Sh, Ph);

    // out = P V
    hmma_gemm_nt<0><<<dim3(DVV / 128, SQB / 128), 256, SMEMSZ>>>(
        Ph, Vth, out, SKK, DVV, 1.f);
}

// round 16
// speedup vs baseline: 1.0590x; 1.0590x over previous
#include <cuda_runtime.h>
#include <cuda_fp16.h>
#include <math.h>
#include <stdint.h>

#define SQB 16384
#define SKK 4096
#define DDK 512
#define DVV 256

// ---------------- scratch ----------------
__device__ __align__(256) __half g_Yh[SKK * DDK];
__device__ __align__(256) __half g_Zh[SKK * DDK];
__device__ __align__(256) __half g_Wkh[DDK * DDK];
__device__ __align__(256) __half g_Wvh[DVV * DDK];
__device__ __align__(256) __half g_Eh[(long long)SQB * SKK];   // exp(scores) fp16
__device__ __align__(256) __half g_Xh[(long long)SQB * DDK];
__device__ __align__(256) __half g_Kh[SKK * DDK];              // projected K fp16
__device__ __align__(256) __half g_Vh[SKK * DVV];              // projected V fp16
__device__ __align__(256) __half g_Vth[DVV * SKK];             // V^T fp16
__device__ __align__(256) float  g_part[SQB * 32];             // per-CTA row partial sums
__device__ __align__(256) float  g_inv[SQB];                   // 1 / rowsum

// ---------------- helpers ----------------
__device__ __forceinline__ uint32_t smem_u32(const void* p) {
    uint32_t a;
    asm("{ .reg .u64 t; cvta.to.shared.u64 t, %1; cvt.u32.u64 %0, t; }" : "=r"(a) : "l"(p));
    return a;
}
__device__ __forceinline__ void cp16(uint32_t s, const void* g) {
    asm volatile("cp.async.cg.shared.global [%0], [%1], 16;"
                 :: "r"(s), "l"(__cvta_generic_to_global(g)) : "memory");
}
#define CP_COMMIT() asm volatile("cp.async.commit_group;" ::: "memory")
#define CP_WAIT(n)  asm volatile("cp.async.wait_group %0;" :: "n"(n) : "memory")

#define LDSM4(r, a) \
    asm volatile("ldmatrix.sync.aligned.m8n8.x4.shared.b16 {%0,%1,%2,%3}, [%4];" \
                 : "=r"((r)[0]), "=r"((r)[1]), "=r"((r)[2]), "=r"((r)[3]) : "r"(a))

#define MMA_F16(d, a, b) \
    asm volatile("mma.sync.aligned.m16n8k16.row.col.f32.f16.f16.f32 " \
                 "{%0,%1,%2,%3}, {%4,%5,%6,%7}, {%8,%9}, {%0,%1,%2,%3};" \
                 : "+f"((d)[0]), "+f"((d)[1]), "+f"((d)[2]), "+f"((d)[3]) \
                 : "r"((a)[0]), "r"((a)[1]), "r"((a)[2]), "r"((a)[3]), \
                   "r"((b)[0]), "r"((b)[1]))

// ---------------- HMMA NT GEMM, single fp16, 128x128 CTA, KC=64, 2 stages --
// MODE 0: fp32 out                     (aux unused)
// MODE 1: fp16 out
// MODE 2: fp16 out = exp(acc*scale), emit per-CTA row partial sums to auxf
// MODE 3: fp32 out = acc * scale * auxc[row]  (row normalization)
#define KC 64
#define ROWB 144                // 128B data + 16B pad per smem row
#define PLANE (128 * ROWB)      // 18432 B
#define OFF_A  0
#define OFF_B  (1 * PLANE)
#define STAGE  (2 * PLANE)      // 36864 B
#define SMEMSZ (2 * STAGE)      // 73728 B  (>= 2KB reused for partials in MODE 2)

__device__ __forceinline__ void load_stage(
    uint32_t base, int tid, int kc0, int Kdim,
    const __half* __restrict__ A, const __half* __restrict__ B,
    long long m0, long long n0)
{
#pragma unroll
    for (int it = 0; it < 4; it++) {
        const int j = tid + it * 256;
        const int row = j >> 3;
        const int part = j & 7;
        const uint32_t off = (uint32_t)row * ROWB + part * 16;
        cp16(base + OFF_A + off, A + (m0 + row) * (long long)Kdim + kc0 + part * 8);
        cp16(base + OFF_B + off, B + (n0 + row) * (long long)Kdim + kc0 + part * 8);
    }
    CP_COMMIT();
}

template <int MODE>
__global__ __launch_bounds__(256)
void hmma_gemm_nt(const __half* __restrict__ A, const __half* __restrict__ B,
                  void* __restrict__ Cv, int Kdim, int ldc, float scale,
                  float* __restrict__ auxf, const float* __restrict__ auxc)
{
    extern __shared__ char sm[];
    const uint32_t sb = smem_u32(sm);

    const int tid  = threadIdx.x;
    const int lane = tid & 31;
    const int wid  = tid >> 5;
    const int wm   = wid & 1;    // 2 warps along M
    const int wn   = wid >> 1;   // 4 warps along N
    const long long m0 = (long long)blockIdx.y * 128;
    const long long n0 = (long long)blockIdx.x * 128;

    float acc[4][4][4];
#pragma unroll
    for (int i = 0; i < 4; i++)
#pragma unroll
        for (int j = 0; j < 4; j++)
#pragma unroll
            for (int k = 0; k < 4; k++) acc[i][j][k] = 0.f;

    const int NC = Kdim / KC;

    load_stage(sb,         tid, 0,  Kdim, A, B, m0, n0);
    load_stage(sb + STAGE, tid, KC, Kdim, A, B, m0, n0);

    const int g = lane >> 3;
    const int r = lane & 7;

    for (int c = 0; c < NC; c++) {
        const int st = c & 1;
        const uint32_t base = sb + st * STAGE;
        if (c + 2 < NC) { CP_WAIT(1); } else { CP_WAIT(0); }
        __syncthreads();

#pragma unroll
        for (int ks = 0; ks < 4; ks++) {
            uint32_t a_f[4][4], b_f[4][2];
#pragma unroll
            for (int mi = 0; mi < 4; mi++) {
                const uint32_t row = wm * 64 + mi * 16 + (g & 1) * 8 + r;
                const uint32_t cb  = ks * 32 + (g >> 1) * 16;
                LDSM4(a_f[mi], base + OFF_A + row * ROWB + cb);
            }
#pragma unroll
            for (int np = 0; np < 2; np++) {
                const uint32_t row = wn * 32 + np * 16 + (g >> 1) * 8 + r;
                const uint32_t cb  = ks * 32 + (g & 1) * 16;
                uint32_t t[4];
                LDSM4(t, base + OFF_B + row * ROWB + cb);
                b_f[np * 2][0] = t[0]; b_f[np * 2][1] = t[1];
                b_f[np * 2 + 1][0] = t[2]; b_f[np * 2 + 1][1] = t[3];
            }
#pragma unroll
            for (int mi = 0; mi < 4; mi++)
#pragma unroll
                for (int ni = 0; ni < 4; ni++)
                    MMA_F16(acc[mi][ni], a_f[mi], b_f[ni]);
        }
        __syncthreads();
        if (c + 2 < NC)
            load_stage(base, tid, (c + 2) * KC, Kdim, A, B, m0, n0);
    }

    // ---------------- epilogues ----------------
    if (MODE == 2) {
        // exp + store fp16 + per-row partial sums
        __half* C = (__half*)Cv;
        float ps0[4], ps1[4];
#pragma unroll
        for (int mi = 0; mi < 4; mi++) { ps0[mi] = 0.f; ps1[mi] = 0.f; }
#pragma unroll
        for (int mi = 0; mi < 4; mi++)
#pragma unroll
            for (int ni = 0; ni < 4; ni++) {
                const long long row = m0 + wm * 64 + mi * 16 + (lane >> 2);
                const long long col = n0 + wn * 32 + ni * 8 + 2 * (lane & 3);
                float e0 = __expf(acc[mi][ni][0] * scale);
                float e1 = __expf(acc[mi][ni][1] * scale);
                float e2 = __expf(acc[mi][ni][2] * scale);
                float e3 = __expf(acc[mi][ni][3] * scale);
                *(__half2*)&C[row * ldc + col]       = __floats2half2_rn(e0, e1);
                *(__half2*)&C[(row + 8) * ldc + col] = __floats2half2_rn(e2, e3);
                ps0[mi] += e0 + e1;
                ps1[mi] += e2 + e3;
            }
        // quad reduce (lanes sharing a row differ only in lane&3)
#pragma unroll
        for (int mi = 0; mi < 4; mi++) {
            ps0[mi] += __shfl_xor_sync(0xffffffffu, ps0[mi], 1);
            ps0[mi] += __shfl_xor_sync(0xffffffffu, ps0[mi], 2);
            ps1[mi] += __shfl_xor_sync(0xffffffffu, ps1[mi], 1);
            ps1[mi] += __shfl_xor_sync(0xffffffffu, ps1[mi], 2);
        }
        __syncthreads();                     // mainloop smem no longer in use
        float* part = (float*)sm;            // [4][128]
        if ((lane & 3) == 0) {
#pragma unroll
            for (int mi = 0; mi < 4; mi++) {
                const int r0 = wm * 64 + mi * 16 + (lane >> 2);
                part[wn * 128 + r0]     = ps0[mi];
                part[wn * 128 + r0 + 8] = ps1[mi];
            }
        }
        __syncthreads();
        if (tid < 128) {
            const float s = part[tid] + part[128 + tid] + part[256 + tid] + part[384 + tid];
            auxf[(m0 + tid) * 32 + blockIdx.x] = s;
        }
    } else {
#pragma unroll
        for (int mi = 0; mi < 4; mi++)
#pragma unroll
            for (int ni = 0; ni < 4; ni++) {
                const long long row = m0 + wm * 64 + mi * 16 + (lane >> 2);
                const long long col = n0 + wn * 32 + ni * 8 + 2 * (lane & 3);
                if (MODE == 1) {
                    __half* C = (__half*)Cv;
                    *(__half2*)&C[row * ldc + col] =
                        __floats2half2_rn(acc[mi][ni][0] * scale, acc[mi][ni][1] * scale);
                    *(__half2*)&C[(row + 8) * ldc + col] =
                        __floats2half2_rn(acc[mi][ni][2] * scale, acc[mi][ni][3] * scale);
                } else if (MODE == 3) {
                    float* C = (float*)Cv;
                    const float i0 = auxc[row] * scale;
                    const float i1 = auxc[row + 8] * scale;
                    *(float2*)&C[row * ldc + col] =
                        make_float2(acc[mi][ni][0] * i0, acc[mi][ni][1] * i0);
                    *(float2*)&C[(row + 8) * ldc + col] =
                        make_float2(acc[mi][ni][2] * i1, acc[mi][ni][3] * i1);
                } else {
                    float* C = (float*)Cv;
                    *(float2*)&C[row * ldc + col] =
                        make_float2(acc[mi][ni][0] * scale, acc[mi][ni][1] * scale);
                    *(float2*)&C[(row + 8) * ldc + col] =
                        make_float2(acc[mi][ni][2] * scale, acc[mi][ni][3] * scale);
                }
            }
    }
}

// ---------------- rowsum reduce: inv[i] = 1 / sum_j part[i*32+j] ------------
__global__ __launch_bounds__(256)
void rowsum_inv_kernel(const float* __restrict__ part, float* __restrict__ inv)
{
    const int i = blockIdx.x * 256 + threadIdx.x;
    const float* p = part + (long long)i * 32;
    float s = 0.f;
#pragma unroll
    for (int j = 0; j < 32; j += 4) {
        float4 v = *(const float4*)&p[j];
        s += v.x + v.y + v.z + v.w;
    }
    inv[i] = 1.0f / s;
}

// ---------------- conversion kernels ----------------
__device__ __forceinline__ uint32_t packh2(__half a, __half b) {
    return (uint32_t)__half_as_ushort(a) | ((uint32_t)__half_as_ushort(b) << 16);
}

__global__ __launch_bounds__(256)
void tohalf_kernel(const float* __restrict__ in, __half* __restrict__ out)
{
    const long long i = (long long)blockIdx.x * 256 + threadIdx.x;
    float4 v = ((const float4*)in)[i];
    ((uint2*)out)[i] = make_uint2(packh2(__float2half_rn(v.x), __float2half_rn(v.y)),
                                  packh2(__float2half_rn(v.z), __float2half_rn(v.w)));
}

// V [4096,256] fp16 -> V^T [256,4096] fp16, 32x32 smem tile transpose
__global__ __launch_bounds__(256)
void vtrans_kernel(const __half* __restrict__ V, __half* __restrict__ th)
{
    __shared__ __half t[32][34];
    const int x = threadIdx.x & 31;
    const int y = threadIdx.x >> 5;
    const int k0 = blockIdx.x * 32;
    const int n0 = blockIdx.y * 32;
#pragma unroll
    for (int i = 0; i < 4; i++)
        t[y + i * 8][x] = V[(long long)(k0 + y + i * 8) * 256 + n0 + x];
    __syncthreads();
#pragma unroll
    for (int i = 0; i < 4; i++)
        th[(long long)(n0 + y + i * 8) * 4096 + k0 + x] = t[x][y + i * 8];
}

// ---------------------------------------------------------------------------
extern "C" void kernel_launch(void* const* d_in, const int* in_sizes, int n_in,
                              void* d_out, int out_size)
{
    (void)in_sizes; (void)n_in; (void)out_size;
    const float* X  = (const float*)d_in[0];
    const float* Y  = (const float*)d_in[1];
    const float* Z  = (const float*)d_in[2];
    const float* Wk = (const float*)d_in[3];
    const float* Wv = (const float*)d_in[4];
    float* out = (float*)d_out;

    __half *Yh, *Zh, *Wkh, *Wvh, *Eh, *Xh, *Kh, *Vh, *Vth;
    float *part, *inv;
    cudaGetSymbolAddress((void**)&Yh,   g_Yh);
    cudaGetSymbolAddress((void**)&Zh,   g_Zh);
    cudaGetSymbolAddress((void**)&Wkh,  g_Wkh);
    cudaGetSymbolAddress((void**)&Wvh,  g_Wvh);
    cudaGetSymbolAddress((void**)&Eh,   g_Eh);
    cudaGetSymbolAddress((void**)&Xh,   g_Xh);
    cudaGetSymbolAddress((void**)&Kh,   g_Kh);
    cudaGetSymbolAddress((void**)&Vh,   g_Vh);
    cudaGetSymbolAddress((void**)&Vth,  g_Vth);
    cudaGetSymbolAddress((void**)&part, g_part);
    cudaGetSymbolAddress((void**)&inv,  g_inv);

    cudaFuncSetAttribute(hmma_gemm_nt<0>, cudaFuncAttributeMaxDynamicSharedMemorySize, SMEMSZ);
    cudaFuncSetAttribute(hmma_gemm_nt<1>, cudaFuncAttributeMaxDynamicSharedMemorySize, SMEMSZ);
    cudaFuncSetAttribute(hmma_gemm_nt<2>, cudaFuncAttributeMaxDynamicSharedMemorySize, SMEMSZ);
    cudaFuncSetAttribute(hmma_gemm_nt<3>, cudaFuncAttributeMaxDynamicSharedMemorySize, SMEMSZ);

    const float rs = 0.0441941738241592f;  // 1/sqrt(512)

    // fp32 -> fp16 conversions of raw inputs
    tohalf_kernel<<<(SQB * DDK) / 1024, 256>>>(X, Xh);
    tohalf_kernel<<<(SKK * DDK) / 1024, 256>>>(Y, Yh);
    tohalf_kernel<<<(SKK * DDK) / 1024, 256>>>(Z, Zh);
    tohalf_kernel<<<(DDK * DDK) / 1024, 256>>>(Wk, Wkh);
    tohalf_kernel<<<(DVV * DDK) / 1024, 256>>>(Wv, Wvh);

    // Projections on HMMA (fp16 in, fp32 accum, fp16 out)
    hmma_gemm_nt<1><<<dim3(DDK / 128, SKK / 128), 256, SMEMSZ>>>(
        Yh, Wkh, Kh, DDK, DDK, 1.f, nullptr, nullptr);
    hmma_gemm_nt<1><<<dim3(DVV / 128, SKK / 128), 256, SMEMSZ>>>(
        Zh, Wvh, Vh, DDK, DVV, 1.f, nullptr, nullptr);

    // V^T (fp16)
    vtrans_kernel<<<dim3(SKK / 32, DVV / 32), 256>>>(Vh, Vth);

    // E = exp(X K^T * rs), plus per-CTA row partial sums (fused softmax pt.1)
    hmma_gemm_nt<2><<<dim3(SKK / 128, SQB / 128), 256, SMEMSZ>>>(
        Xh, Kh, Eh, DDK, SKK, rs, part, nullptr);

    // inv[row] = 1 / rowsum
    rowsum_inv_kernel<<<SQB / 256, 256>>>(part, inv);

    // out = (E V) * inv[row]  (fused softmax pt.2)
    hmma_gemm_nt<3><<<dim3(DVV / 128, SQB / 128), 256, SMEMSZ>>>(
        Eh, Vth, out, SKK, DVV, 1.f, nullptr, inv);
}